// round 3
// baseline (speedup 1.0000x reference)
#include <cuda_runtime.h>
#include <cuda_bf16.h>
#include <cstdint>
#include <math.h>

// ---------------- problem constants ----------------
#define N_UTT   2000
#define NODES   6000
#define ND      200      // n_dim == nhidden
#define ND2     400      // 2*nhidden (variant=True support width)
#define HBW     256      // padded width of bf16 h buffer
#define MPAD    6048     // 63 * 96, padded adj rows
#define NLAYERS 8

// ---------------- device scratch (no allocation allowed) ----------------
static __device__ __nv_bfloat16 g_adjBF[(size_t)MPAD * NODES];   // 72.6 MB
static __device__ __nv_bfloat16 g_Hbf[(size_t)NODES * HBW];      // bf16 h, cols 200..255 zero
static __device__ float g_X [(size_t)NODES * ND];                // x (post-projection features)
static __device__ float g_H0[(size_t)NODES * ND];                // h0
static __device__ float g_Hf[(size_t)NODES * ND];                // current h (fp32)
static __device__ float g_SUP[(size_t)NODES * ND2];              // [hi | h0]

// ---------------- small PTX helpers ----------------
__device__ __forceinline__ void cp16(void* s, const void* g) {
    uint32_t sa = (uint32_t)__cvta_generic_to_shared(s);
    asm volatile("cp.async.cg.shared.global [%0], [%1], 16;\n" :: "r"(sa), "l"(g));
}
__device__ __forceinline__ void cp_commit() { asm volatile("cp.async.commit_group;\n" ::); }
__device__ __forceinline__ void cp_wait1()  { asm volatile("cp.async.wait_group 1;\n" ::); }
__device__ __forceinline__ void cp_wait0()  { asm volatile("cp.async.wait_group 0;\n" ::); }

__device__ __forceinline__ void ldsm_x4(uint32_t* r, const void* p) {
    uint32_t sa = (uint32_t)__cvta_generic_to_shared(p);
    asm volatile("ldmatrix.sync.aligned.m8n8.x4.shared.b16 {%0,%1,%2,%3}, [%4];\n"
                 : "=r"(r[0]), "=r"(r[1]), "=r"(r[2]), "=r"(r[3]) : "r"(sa));
}
__device__ __forceinline__ void ldsm_x4_t(uint32_t* r, const void* p) {
    uint32_t sa = (uint32_t)__cvta_generic_to_shared(p);
    asm volatile("ldmatrix.sync.aligned.m8n8.x4.trans.shared.b16 {%0,%1,%2,%3}, [%4];\n"
                 : "=r"(r[0]), "=r"(r[1]), "=r"(r[2]), "=r"(r[3]) : "r"(sa));
}
__device__ __forceinline__ void mma_bf16(float* c, const uint32_t* a, const uint32_t* b) {
    asm volatile("mma.sync.aligned.m16n8k16.row.col.f32.bf16.bf16.f32 "
                 "{%0,%1,%2,%3},{%4,%5,%6,%7},{%8,%9},{%0,%1,%2,%3};\n"
                 : "+f"(c[0]), "+f"(c[1]), "+f"(c[2]), "+f"(c[3])
                 : "r"(a[0]), "r"(a[1]), "r"(a[2]), "r"(a[3]), "r"(b[0]), "r"(b[1]));
}
__device__ __forceinline__ void mma_tf32(float* c, uint32_t a0, uint32_t a1, uint32_t a2,
                                         uint32_t a3, uint32_t b0, uint32_t b1) {
    asm volatile("mma.sync.aligned.m16n8k8.row.col.f32.tf32.tf32.f32 "
                 "{%0,%1,%2,%3},{%4,%5,%6,%7},{%8,%9},{%0,%1,%2,%3};\n"
                 : "+f"(c[0]), "+f"(c[1]), "+f"(c[2]), "+f"(c[3])
                 : "r"(a0), "r"(a1), "r"(a2), "r"(a3), "r"(b0), "r"(b1));
}
__device__ __forceinline__ uint32_t f2tf32(float x) {
    uint32_t r; asm("cvt.rna.tf32.f32 %0, %1;" : "=r"(r) : "f"(x)); return r;
}

// ---------------- adj fp32 -> bf16 (rows >= NODES zero-filled) ----------------
__global__ void k_conv_adj(const float* __restrict__ adj) {
    size_t i4 = (size_t)blockIdx.x * blockDim.x + threadIdx.x;
    size_t total = (size_t)MPAD * NODES / 4;
    if (i4 >= total) return;
    size_t e = i4 * 4;
    size_t r = e / NODES;           // NODES % 4 == 0 -> a float4 never crosses rows
    __nv_bfloat162 o01, o23;
    if (r < NODES) {
        float4 v = *reinterpret_cast<const float4*>(adj + e);
        o01 = __floats2bfloat162_rn(v.x, v.y);
        o23 = __floats2bfloat162_rn(v.z, v.w);
    } else {
        o01 = __floats2bfloat162_rn(0.f, 0.f);
        o23 = o01;
    }
    *reinterpret_cast<__nv_bfloat162*>(g_adjBF + e)     = o01;
    *reinterpret_cast<__nv_bfloat162*>(g_adjBF + e + 2) = o23;
}

// zero the padded columns (200..255) of g_Hbf once per launch (deterministic)
__global__ void k_zero_pad() {
    int i = blockIdx.x * blockDim.x + threadIdx.x;
    if (i < NODES * (HBW - ND)) {
        int r = i / (HBW - ND), c = ND + i % (HBW - ND);
        g_Hbf[(size_t)r * HBW + c] = __float2bfloat16(0.0f);
    }
}

// ---------------- GEMM1: SUP[:,0:200] = adjBF @ Hbf  (bf16 MMA, fp32 accum) ----------------
// grid (63, 2), 256 threads. BM=96, BN=128, BK=48.
#define G1_BM 96
#define G1_BN 128
#define G1_BK 48
__global__ __launch_bounds__(256) void k_gemm_adj() {
    __shared__ __nv_bfloat16 sA[2][G1_BM][56];   // 48 cols + 8 pad (112B rows)
    __shared__ __nv_bfloat16 sB[2][G1_BK][136];  // 128 cols + 8 pad (272B rows)

    const int tid  = threadIdx.x;
    const int lane = tid & 31;
    const int warp = tid >> 5;
    const int wm   = warp >> 2;      // 0..1 (48 rows each)
    const int wn   = warp & 3;       // 0..3 (32 cols each)
    const int bm0  = blockIdx.x * G1_BM;
    const int bn0  = blockIdx.y * G1_BN;

    float acc[3][4][4];
    #pragma unroll
    for (int i = 0; i < 3; i++)
        #pragma unroll
        for (int j = 0; j < 4; j++)
            #pragma unroll
            for (int k = 0; k < 4; k++) acc[i][j][k] = 0.f;

    auto load_tiles = [&](int st, int it) {
        const int k0 = it * G1_BK;
        for (int v = tid; v < (G1_BM * G1_BK / 8); v += 256) {   // 576 vec8
            int m = v / 6, kc = (v % 6) * 8;
            cp16(&sA[st][m][kc], g_adjBF + (size_t)(bm0 + m) * NODES + k0 + kc);
        }
        for (int v = tid; v < (G1_BK * G1_BN / 8); v += 256) {   // 768 vec8
            int k = v / 16, nc = (v % 16) * 8;
            cp16(&sB[st][k][nc], g_Hbf + (size_t)(k0 + k) * HBW + bn0 + nc);
        }
        cp_commit();
    };

    const int ITERS = NODES / G1_BK;   // 125
    load_tiles(0, 0);

    #pragma unroll 1
    for (int it = 0; it < ITERS; ++it) {
        if (it + 1 < ITERS) { load_tiles((it + 1) & 1, it + 1); cp_wait1(); }
        else                { cp_wait0(); }
        __syncthreads();
        const int st = it & 1;
        #pragma unroll
        for (int ks = 0; ks < 3; ks++) {
            uint32_t afr[3][4];
            #pragma unroll
            for (int mf = 0; mf < 3; mf++)
                ldsm_x4(afr[mf], &sA[st][wm * 48 + mf * 16 + (lane & 15)]
                                    [ks * 16 + ((lane >> 4) << 3)]);
            uint32_t bfr[4][2];
            #pragma unroll
            for (int nh = 0; nh < 2; nh++) {
                uint32_t r[4];
                ldsm_x4_t(r, &sB[st][ks * 16 + (lane & 15)]
                                    [wn * 32 + nh * 16 + ((lane >> 4) << 3)]);
                bfr[nh * 2][0] = r[0]; bfr[nh * 2][1] = r[1];
                bfr[nh * 2 + 1][0] = r[2]; bfr[nh * 2 + 1][1] = r[3];
            }
            #pragma unroll
            for (int mf = 0; mf < 3; mf++)
                #pragma unroll
                for (int nf = 0; nf < 4; nf++)
                    mma_bf16(acc[mf][nf], afr[mf], bfr[nf]);
        }
        __syncthreads();
    }

    // epilogue -> SUP[:,0:200]
    const int base_m = bm0 + wm * 48;
    const int base_n = bn0 + wn * 32;
    #pragma unroll
    for (int mf = 0; mf < 3; mf++)
        #pragma unroll
        for (int nf = 0; nf < 4; nf++) {
            int r = base_m + mf * 16 + (lane >> 2);
            int c = base_n + nf * 8 + ((lane & 3) << 1);
            float* a = acc[mf][nf];
            if (r < NODES) {
                if (c     < ND) g_SUP[(size_t)r * ND2 + c]     = a[0];
                if (c + 1 < ND) g_SUP[(size_t)r * ND2 + c + 1] = a[1];
            }
            int r2 = r + 8;
            if (r2 < NODES) {
                if (c     < ND) g_SUP[(size_t)r2 * ND2 + c]     = a[2];
                if (c + 1 < ND) g_SUP[(size_t)r2 * ND2 + c + 1] = a[3];
            }
        }
}

// ---------------- GEMM2: tf32 MMA, C = A[M,K] @ W[K,200], fused epilogues ----------------
// BM=64, BN=208 (full width), BK=16. 256 threads, warp tile 16x104.
// mode 0: X[row_off+m] = acc + bias
// mode 1: X[row_off+m] = acc + bias + spk_emb[argmax(qmask)]
// mode 2: h0 = relu(acc+bias) -> H0, SUP[:,200:400], Hbf
// mode 3: h  = relu(theta*acc + (1-theta)*(0.9*SUP[:,0:200] + 0.1*H0)) -> Hf, Hbf
#define G2_BM 64
#define G2_BN 208
#define G2_BK 16
__global__ __launch_bounds__(256) void k_gemm_tf32(
    const float* __restrict__ Aext, int asel, int lda, int M, int K,
    const float* __restrict__ W, const float* __restrict__ bias,
    int mode, float theta, int row_off,
    const float* __restrict__ qmask, const float* __restrict__ spk_emb)
{
    __shared__ uint32_t sAm[G2_BK][G2_BM + 1];   // [k][m]
    __shared__ uint32_t sBm[G2_BK][G2_BN + 1];   // [k][n]

    const float* A = (asel == 1) ? g_X : (asel == 2) ? g_SUP : Aext;

    const int tid  = threadIdx.x;
    const int lane = tid & 31;
    const int warp = tid >> 5;
    const int wm   = warp >> 1;   // 0..3
    const int wn   = warp & 1;    // 0..1
    const int bm0  = blockIdx.x * G2_BM;

    float acc[13][4];
    #pragma unroll
    for (int i = 0; i < 13; i++)
        #pragma unroll
        for (int j = 0; j < 4; j++) acc[i][j] = 0.f;

    const int ITERS = (K + G2_BK - 1) / G2_BK;
    for (int it = 0; it < ITERS; ++it) {
        const int k0 = it * G2_BK;
        __syncthreads();
        // load A tile (coalesced along k within a row)
        for (int v = tid; v < G2_BM * G2_BK; v += 256) {
            int k = v & 15, m = v >> 4;
            int gm = bm0 + m, gk = k0 + k;
            float val = (gm < M && gk < K) ? A[(size_t)gm * lda + gk] : 0.f;
            sAm[k][m] = f2tf32(val);
        }
        // load W tile (coalesced along n)
        for (int v = tid; v < G2_BK * G2_BN; v += 256) {
            int k = v / G2_BN, n = v % G2_BN;
            int gk = k0 + k;
            float val = (gk < K && n < ND) ? W[(size_t)gk * ND + n] : 0.f;
            sBm[k][n] = f2tf32(val);
        }
        __syncthreads();

        #pragma unroll
        for (int kb = 0; kb < G2_BK; kb += 8) {
            int mrow = wm * 16 + (lane >> 2);
            int kk   = kb + (lane & 3);
            uint32_t a0 = sAm[kk][mrow],     a1 = sAm[kk][mrow + 8];
            uint32_t a2 = sAm[kk + 4][mrow], a3 = sAm[kk + 4][mrow + 8];
            #pragma unroll
            for (int nf = 0; nf < 13; nf++) {
                int nc = wn * 104 + nf * 8 + (lane >> 2);
                uint32_t b0 = sBm[kb + (lane & 3)][nc];
                uint32_t b1 = sBm[kb + 4 + (lane & 3)][nc];
                mma_tf32(acc[nf], a0, a1, a2, a3, b0, b1);
            }
        }
    }

    // fused epilogue
    auto epi = [&](int m, int n, float v) {
        if (m >= M || n >= ND) return;
        if (mode == 0 || mode == 1) {
            float x = v + bias[n];
            if (mode == 1) {
                int b = m / 100, t = m % 100;
                float q0 = qmask[(t * 20 + b) * 2];
                float q1 = qmask[(t * 20 + b) * 2 + 1];
                int idx = (q1 > q0) ? 1 : 0;
                x += spk_emb[idx * ND + n];
            }
            g_X[(size_t)(row_off + m) * ND + n] = x;
        } else if (mode == 2) {
            float x = fmaxf(v + bias[n], 0.f);
            g_H0[(size_t)m * ND + n] = x;
            g_SUP[(size_t)m * ND2 + ND + n] = x;
            g_Hbf[(size_t)m * HBW + n] = __float2bfloat16(x);
        } else {  // mode 3
            float hi  = g_SUP[(size_t)m * ND2 + n];
            float h0v = g_H0[(size_t)m * ND + n];
            float x = theta * v + (1.f - theta) * (0.9f * hi + 0.1f * h0v);
            x = fmaxf(x, 0.f);
            g_Hf[(size_t)m * ND + n] = x;
            g_Hbf[(size_t)m * HBW + n] = __float2bfloat16(x);
        }
    };

    const int mloc = wm * 16 + (lane >> 2);
    #pragma unroll
    for (int nf = 0; nf < 13; nf++) {
        int c = wn * 104 + nf * 8 + ((lane & 3) << 1);
        epi(bm0 + mloc,     c,     acc[nf][0]);
        epi(bm0 + mloc,     c + 1, acc[nf][1]);
        epi(bm0 + mloc + 8, c,     acc[nf][2]);
        epi(bm0 + mloc + 8, c + 1, acc[nf][3]);
    }
}

// ---------------- output assembly: [2000, 1200] ----------------
__global__ void k_out(float* __restrict__ out) {
    int i = blockIdx.x * blockDim.x + threadIdx.x;
    if (i >= N_UTT * 1200) return;
    int r = i / 1200, c = i % 1200;
    int seg = c / ND, cc = c % ND;
    int chunk = seg >> 1;
    const float* src = (seg & 1) ? g_Hf : g_X;
    out[i] = src[(size_t)(chunk * N_UTT + r) * ND + cc];
}

// ---------------- launch ----------------
extern "C" void kernel_launch(void* const* d_in, const int* in_sizes, int n_in,
                              void* d_out, int out_size) {
    const float* a    = (const float*)d_in[0];
    const float* v    = (const float*)d_in[1];
    const float* l    = (const float*)d_in[2];
    const float* qm   = (const float*)d_in[3];
    const float* adj  = (const float*)d_in[4];
    const float* Wa   = (const float*)d_in[5];
    const float* ba   = (const float*)d_in[6];
    const float* Wv   = (const float*)d_in[7];
    const float* bv   = (const float*)d_in[8];
    const float* Wl   = (const float*)d_in[9];
    const float* bl   = (const float*)d_in[10];
    const float* spk  = (const float*)d_in[11];
    const float* W0   = (const float*)d_in[12];
    const float* b0   = (const float*)d_in[13];
    const float* convW= (const float*)d_in[14];
    float* out = (float*)d_out;

    // 1. adj -> bf16 (padded rows zero-filled)
    {
        size_t total4 = (size_t)MPAD * NODES / 4;
        k_conv_adj<<<(unsigned)((total4 + 255) / 256), 256>>>(adj);
    }
    k_zero_pad<<<(NODES * (HBW - ND) + 255) / 256, 256>>>();

    // 2. modality projections -> X
    k_gemm_tf32<<<(N_UTT + G2_BM - 1) / G2_BM, 256>>>(a, 0, 300,  N_UTT, 300,  Wa, ba, 0, 0.f, 0,    nullptr, nullptr);
    k_gemm_tf32<<<(N_UTT + G2_BM - 1) / G2_BM, 256>>>(v, 0, 342,  N_UTT, 342,  Wv, bv, 0, 0.f, 2000, nullptr, nullptr);
    k_gemm_tf32<<<(N_UTT + G2_BM - 1) / G2_BM, 256>>>(l, 0, 1024, N_UTT, 1024, Wl, bl, 1, 0.f, 4000, qm, spk);

    // 3. h0 = relu(X @ W0 + b0) -> H0, SUP[:,200:400], Hbf
    k_gemm_tf32<<<(NODES + G2_BM - 1) / G2_BM, 256>>>(nullptr, 1, ND, NODES, ND, W0, b0, 2, 0.f, 0, nullptr, nullptr);

    // 4. GCNII layers
    for (int k = 0; k < NLAYERS; ++k) {
        float theta = logf(0.5f / (float)(k + 1) + 1.0f);
        dim3 g1(MPAD / G1_BM, 2);
        k_gemm_adj<<<g1, 256>>>();
        k_gemm_tf32<<<(NODES + G2_BM - 1) / G2_BM, 256>>>(
            nullptr, 2, ND2, NODES, ND2, convW + (size_t)k * ND2 * ND,
            nullptr, 3, theta, 0, nullptr, nullptr);
    }

    // 5. gather output
    k_out<<<(N_UTT * 1200 + 255) / 256, 256>>>(out);
}

// round 5
// speedup vs baseline: 1.9731x; 1.9731x over previous
#include <cuda_runtime.h>
#include <cuda_bf16.h>
#include <cstdint>
#include <math.h>

// ---------------- problem constants ----------------
#define N_UTT   2000
#define NODES   6000
#define KPAD    6016     // padded node count (94*64, 188*32)
#define ND      200      // n_dim == nhidden
#define NDP     208      // padded feature width
#define ND2     400      // 2*nhidden
#define NLAYERS 8

// ---------------- device scratch (no allocation allowed) ----------------
static __device__ __nv_bfloat16 g_adjBF[(size_t)KPAD * KPAD];    // 72.4 MB, zero-padded
static __device__ __nv_bfloat16 g_Hbf[(size_t)KPAD * NDP];       // h bf16 [node][feat], pads 0
static __device__ float g_X [(size_t)NODES * ND];
static __device__ float g_H0[(size_t)NODES * ND];
static __device__ float g_Hf[(size_t)NODES * ND];
static __device__ float g_SUP[(size_t)NODES * ND2];              // [hi | h0]
static __device__ __align__(16) float g_zeroF[4];                // zero-initialized

// ---------------- PTX helpers ----------------
__device__ __forceinline__ void cp16(void* s, const void* g) {
    uint32_t sa = (uint32_t)__cvta_generic_to_shared(s);
    asm volatile("cp.async.cg.shared.global [%0], [%1], 16;\n" :: "r"(sa), "l"(g));
}
__device__ __forceinline__ void cp8(void* s, const void* g) {
    uint32_t sa = (uint32_t)__cvta_generic_to_shared(s);
    asm volatile("cp.async.ca.shared.global [%0], [%1], 8;\n" :: "r"(sa), "l"(g));
}
__device__ __forceinline__ void cp_commit() { asm volatile("cp.async.commit_group;\n" ::); }

__device__ __forceinline__ void ldsm_x4(uint32_t* r, const void* p) {
    uint32_t sa = (uint32_t)__cvta_generic_to_shared(p);
    asm volatile("ldmatrix.sync.aligned.m8n8.x4.shared.b16 {%0,%1,%2,%3}, [%4];\n"
                 : "=r"(r[0]), "=r"(r[1]), "=r"(r[2]), "=r"(r[3]) : "r"(sa));
}
__device__ __forceinline__ void ldsm_x4_t(uint32_t* r, const void* p) {
    uint32_t sa = (uint32_t)__cvta_generic_to_shared(p);
    asm volatile("ldmatrix.sync.aligned.m8n8.x4.trans.shared.b16 {%0,%1,%2,%3}, [%4];\n"
                 : "=r"(r[0]), "=r"(r[1]), "=r"(r[2]), "=r"(r[3]) : "r"(sa));
}
__device__ __forceinline__ void ldsm_x2_t(uint32_t* r, const void* p) {
    uint32_t sa = (uint32_t)__cvta_generic_to_shared(p);
    asm volatile("ldmatrix.sync.aligned.m8n8.x2.trans.shared.b16 {%0,%1}, [%2];\n"
                 : "=r"(r[0]), "=r"(r[1]) : "r"(sa));
}
__device__ __forceinline__ void mma_bf16(float* c, const uint32_t* a, const uint32_t* b) {
    asm volatile("mma.sync.aligned.m16n8k16.row.col.f32.bf16.bf16.f32 "
                 "{%0,%1,%2,%3},{%4,%5,%6,%7},{%8,%9},{%0,%1,%2,%3};\n"
                 : "+f"(c[0]), "+f"(c[1]), "+f"(c[2]), "+f"(c[3])
                 : "r"(a[0]), "r"(a[1]), "r"(a[2]), "r"(a[3]), "r"(b[0]), "r"(b[1]));
}
__device__ __forceinline__ void mma_tf32(float* c, uint32_t a0, uint32_t a1, uint32_t a2,
                                         uint32_t a3, uint32_t b0, uint32_t b1) {
    asm volatile("mma.sync.aligned.m16n8k8.row.col.f32.tf32.tf32.f32 "
                 "{%0,%1,%2,%3},{%4,%5,%6,%7},{%8,%9},{%0,%1,%2,%3};\n"
                 : "+f"(c[0]), "+f"(c[1]), "+f"(c[2]), "+f"(c[3])
                 : "r"(a0), "r"(a1), "r"(a2), "r"(a3), "r"(b0), "r"(b1));
}
__device__ __forceinline__ uint32_t f2tf32(float x) {
    uint32_t r; asm("cvt.rna.tf32.f32 %0, %1;" : "=r"(r) : "f"(x)); return r;
}

// ---------------- adj fp32 -> bf16 padded [KPAD x KPAD] ----------------
__global__ void k_conv_adj(const float* __restrict__ adj) {
    size_t idx = (size_t)blockIdx.x * blockDim.x + threadIdx.x;
    if (idx >= (size_t)KPAD * (KPAD / 8)) return;
    int r  = (int)(idx / (KPAD / 8));
    int c0 = (int)(idx % (KPAD / 8)) * 8;
    __align__(16) __nv_bfloat162 o[4];
    if (r < NODES && c0 + 8 <= NODES) {
        const float4 v0 = *reinterpret_cast<const float4*>(adj + (size_t)r * NODES + c0);
        const float4 v1 = *reinterpret_cast<const float4*>(adj + (size_t)r * NODES + c0 + 4);
        o[0] = __floats2bfloat162_rn(v0.x, v0.y);
        o[1] = __floats2bfloat162_rn(v0.z, v0.w);
        o[2] = __floats2bfloat162_rn(v1.x, v1.y);
        o[3] = __floats2bfloat162_rn(v1.z, v1.w);
    } else {
        #pragma unroll
        for (int j = 0; j < 4; j++) {
            int c = c0 + j * 2;
            float x0 = (r < NODES && c     < NODES) ? adj[(size_t)r * NODES + c]     : 0.f;
            float x1 = (r < NODES && c + 1 < NODES) ? adj[(size_t)r * NODES + c + 1] : 0.f;
            o[j] = __floats2bfloat162_rn(x0, x1);
        }
    }
    *reinterpret_cast<uint4*>(g_adjBF + (size_t)r * KPAD + c0) =
        *reinterpret_cast<const uint4*>(o);
}

// zero whole bf16 h buffer each launch (pads stay zero; valid region overwritten later)
__global__ void k_zero_hbf() {
    size_t i = (size_t)blockIdx.x * blockDim.x + threadIdx.x;
    if (i < (size_t)KPAD * NDP * sizeof(__nv_bfloat16) / 16)
        reinterpret_cast<uint4*>(g_Hbf)[i] = make_uint4(0, 0, 0, 0);
}

// ---------------- adj GEMM: SUP[:,0:200] = adjBF[KPAD,KPAD] @ Hbf[KPAD,208] -------------
// bf16 mma.sync m16n8k16, fp32 accum. BM=64, BN=208, BK=32, 4-stage cp.async.
// 256 threads = 8 warps: wm = warp>>1 (0..3, 16 rows each), wn = warp&1 (0..1, 104 cols).
#define AB_BM 64
#define AB_BK 32
#define AB_STAGES 4
#define AB_A_EL (AB_BM * 40)          // [64][32+8] bf16
#define AB_B_EL (AB_BK * 216)         // [32][208+8] bf16
#define AB_A_TOT (AB_STAGES * AB_A_EL)
#define AB_SMEM_BYTES ((AB_A_TOT + AB_STAGES * AB_B_EL) * 2)   // 75776

__global__ __launch_bounds__(256, 1) void k_adj_bf16() {
    extern __shared__ __nv_bfloat16 sm[];
    __nv_bfloat16* sA = sm;                 // 4 stages of [64][40]
    __nv_bfloat16* sB = sm + AB_A_TOT;      // 4 stages of [32][216]

    const int tid  = threadIdx.x;
    const int lane = tid & 31;
    const int warp = tid >> 5;
    const int wm   = warp >> 1;
    const int wn   = warp & 1;
    const int bm0  = blockIdx.x * AB_BM;

    float acc[13][4];
    #pragma unroll
    for (int i = 0; i < 13; i++)
        #pragma unroll
        for (int j = 0; j < 4; j++) acc[i][j] = 0.f;

    auto fill = [&](int st, int it) {
        const int k0 = it * AB_BK;
        // A tile: 64 rows x 32 k -> 256 vec8 chunks, one per thread
        {
            int m = tid >> 2, kc = (tid & 3) * 8;
            cp16(sA + st * AB_A_EL + m * 40 + kc,
                 g_adjBF + (size_t)(bm0 + m) * KPAD + k0 + kc);
        }
        // B tile: 32 rows x 208 cols -> 832 vec8 chunks
        #pragma unroll
        for (int v = tid; v < 832; v += 256) {
            int r = v / 26, nc = (v % 26) * 8;
            cp16(sB + st * AB_B_EL + r * 216 + nc,
                 g_Hbf + (size_t)(k0 + r) * NDP + nc);
        }
        cp_commit();
    };

    const int ITERS = KPAD / AB_BK;   // 188
    fill(0, 0); fill(1, 1); fill(2, 2);

    #pragma unroll 1
    for (int it = 0; it < ITERS; ++it) {
        if (it + 3 < ITERS) fill((it + 3) & 3, it + 3);
        else                cp_commit();          // keep group count uniform
        asm volatile("cp.async.wait_group 3;" ::: "memory");
        __syncthreads();
        const int st = it & 3;
        const __nv_bfloat16* a0 = sA + st * AB_A_EL;
        const __nv_bfloat16* b0 = sB + st * AB_B_EL;
        #pragma unroll
        for (int ks = 0; ks < 2; ks++) {
            uint32_t af[4];
            ldsm_x4(af, a0 + (wm * 16 + (lane & 15)) * 40 + ks * 16 + ((lane >> 4) << 3));
            uint32_t bf[13][2];
            #pragma unroll
            for (int ng = 0; ng < 6; ng++) {
                uint32_t r[4];
                ldsm_x4_t(r, b0 + (ks * 16 + (lane & 15)) * 216
                                + wn * 104 + ng * 16 + ((lane >> 4) << 3));
                bf[ng * 2][0] = r[0];     bf[ng * 2][1] = r[1];
                bf[ng * 2 + 1][0] = r[2]; bf[ng * 2 + 1][1] = r[3];
            }
            {
                uint32_t r[2];
                ldsm_x2_t(r, b0 + (ks * 16 + (lane & 15)) * 216 + wn * 104 + 96);
                bf[12][0] = r[0]; bf[12][1] = r[1];
            }
            #pragma unroll
            for (int nf = 0; nf < 13; nf++) mma_bf16(acc[nf], af, bf[nf]);
        }
        __syncthreads();
    }

    // epilogue -> SUP[:,0:200] (float2 stores, c always even)
    const int r0 = bm0 + wm * 16 + (lane >> 2);
    #pragma unroll
    for (int nf = 0; nf < 13; nf++) {
        int c = wn * 104 + nf * 8 + ((lane & 3) << 1);
        if (c < ND) {
            if (r0 < NODES)
                *reinterpret_cast<float2*>(&g_SUP[(size_t)r0 * ND2 + c]) =
                    make_float2(acc[nf][0], acc[nf][1]);
            if (r0 + 8 < NODES)
                *reinterpret_cast<float2*>(&g_SUP[(size_t)(r0 + 8) * ND2 + c]) =
                    make_float2(acc[nf][2], acc[nf][3]);
        }
    }
}

// ---------------- GEMM2: tf32 MMA, C = A[M,K] @ W[K,200], cp.async pipelined ------------
// mode 0: X[row_off+m] = acc + bias
// mode 1: X[row_off+m] = acc + bias + spk_emb[argmax(qmask)]
// mode 2: h0 = relu(acc+bias) -> H0, SUP[:,200:400], Hbf
// mode 3: h  = relu(theta*acc + (1-theta)*(0.9*hi + 0.1*h0)) -> Hf, Hbf
#define G2_BM 64
#define G2_BN 208
#define G2_BK 16
__global__ __launch_bounds__(256) void k_gemm_tf32(
    const float* __restrict__ Aext, int asel, int lda, int M, int K,
    const float* __restrict__ W, const float* __restrict__ bias,
    int mode, float theta, int row_off,
    const float* __restrict__ qmask, const float* __restrict__ spk_emb)
{
    __shared__ float shA[2][G2_BM][G2_BK + 2];
    __shared__ float shB[2][G2_BK][G2_BN + 8];

    const float* A = (asel == 1) ? g_X : (asel == 2) ? g_SUP : Aext;

    const int tid  = threadIdx.x;
    const int lane = tid & 31;
    const int warp = tid >> 5;
    const int wm   = warp >> 1;   // 0..3
    const int wn   = warp & 1;    // 0..1
    const int bm0  = blockIdx.x * G2_BM;

    float acc[13][4];
    #pragma unroll
    for (int i = 0; i < 13; i++)
        #pragma unroll
        for (int j = 0; j < 4; j++) acc[i][j] = 0.f;

    auto fill = [&](int st, int it) {
        const int k0 = it * G2_BK;
        // A tile: 64 rows x 16 k, 8B chunks -> 512
        #pragma unroll
        for (int v = tid; v < 512; v += 256) {
            int m = v >> 3, kp = (v & 7) * 2;
            int gm = bm0 + m, gk = k0 + kp;
            const float* src = (gm < M && gk < K) ? &A[(size_t)gm * lda + gk] : g_zeroF;
            cp8(&shA[st][m][kp], src);
        }
        // B tile: 16 k x 208 n, 8B chunks -> 1664
        for (int v = tid; v < 1664; v += 256) {
            int k = v / 104, np = (v % 104) * 2;
            int gk = k0 + k;
            const float* src = (gk < K && np < ND) ? &W[(size_t)gk * ND + np] : g_zeroF;
            cp8(&shB[st][k][np], src);
        }
        cp_commit();
    };

    const int ITERS = (K + G2_BK - 1) / G2_BK;
    fill(0, 0);

    const int mrow = wm * 16 + (lane >> 2);
    #pragma unroll 1
    for (int it = 0; it < ITERS; ++it) {
        if (it + 1 < ITERS) {
            fill((it + 1) & 1, it + 1);
            asm volatile("cp.async.wait_group 1;" ::: "memory");
        } else {
            asm volatile("cp.async.wait_group 0;" ::: "memory");
        }
        __syncthreads();
        const int st = it & 1;
        #pragma unroll
        for (int kb = 0; kb < G2_BK; kb += 8) {
            const int kk = kb + (lane & 3);
            uint32_t a0 = f2tf32(shA[st][mrow][kk]);
            uint32_t a1 = f2tf32(shA[st][mrow + 8][kk]);
            uint32_t a2 = f2tf32(shA[st][mrow][kk + 4]);
            uint32_t a3 = f2tf32(shA[st][mrow + 8][kk + 4]);
            #pragma unroll
            for (int nf = 0; nf < 13; nf++) {
                int nc = wn * 104 + nf * 8 + (lane >> 2);
                uint32_t b0 = f2tf32(shB[st][kb + (lane & 3)][nc]);
                uint32_t b1 = f2tf32(shB[st][kb + 4 + (lane & 3)][nc]);
                mma_tf32(acc[nf], a0, a1, a2, a3, b0, b1);
            }
        }
        __syncthreads();
    }

    // fused epilogue (pair-wise; c always even)
    const int mloc = wm * 16 + (lane >> 2);
    #pragma unroll
    for (int nf = 0; nf < 13; nf++) {
        int c = wn * 104 + nf * 8 + ((lane & 3) << 1);
        if (c >= ND) continue;            // pairs fully in range iff c <= 198
        #pragma unroll
        for (int half = 0; half < 2; half++) {
            int m = bm0 + mloc + half * 8;
            if (m >= M) continue;
            float v0 = acc[nf][half * 2], v1 = acc[nf][half * 2 + 1];
            if (mode <= 1) {
                float x0 = v0 + bias[c], x1 = v1 + bias[c + 1];
                if (mode == 1) {
                    int b = m / 100, t = m % 100;
                    float q0 = qmask[(t * 20 + b) * 2];
                    float q1 = qmask[(t * 20 + b) * 2 + 1];
                    int idx = (q1 > q0) ? 1 : 0;
                    x0 += spk_emb[idx * ND + c];
                    x1 += spk_emb[idx * ND + c + 1];
                }
                *reinterpret_cast<float2*>(&g_X[(size_t)(row_off + m) * ND + c]) =
                    make_float2(x0, x1);
            } else if (mode == 2) {
                float x0 = fmaxf(v0 + bias[c], 0.f);
                float x1 = fmaxf(v1 + bias[c + 1], 0.f);
                *reinterpret_cast<float2*>(&g_H0[(size_t)m * ND + c]) = make_float2(x0, x1);
                *reinterpret_cast<float2*>(&g_SUP[(size_t)m * ND2 + ND + c]) = make_float2(x0, x1);
                *reinterpret_cast<__nv_bfloat162*>(&g_Hbf[(size_t)m * NDP + c]) =
                    __floats2bfloat162_rn(x0, x1);
            } else {
                float2 hi  = *reinterpret_cast<const float2*>(&g_SUP[(size_t)m * ND2 + c]);
                float2 h0v = *reinterpret_cast<const float2*>(&g_H0[(size_t)m * ND + c]);
                float x0 = fmaxf(theta * v0 + (1.f - theta) * (0.9f * hi.x + 0.1f * h0v.x), 0.f);
                float x1 = fmaxf(theta * v1 + (1.f - theta) * (0.9f * hi.y + 0.1f * h0v.y), 0.f);
                *reinterpret_cast<float2*>(&g_Hf[(size_t)m * ND + c]) = make_float2(x0, x1);
                *reinterpret_cast<__nv_bfloat162*>(&g_Hbf[(size_t)m * NDP + c]) =
                    __floats2bfloat162_rn(x0, x1);
            }
        }
    }
}

// ---------------- output assembly: [2000, 1200] ----------------
__global__ void k_out(float* __restrict__ out) {
    int i = blockIdx.x * blockDim.x + threadIdx.x;
    if (i >= N_UTT * 1200) return;
    int r = i / 1200, c = i % 1200;
    int seg = c / ND, cc = c % ND;
    int chunk = seg >> 1;
    const float* src = (seg & 1) ? g_Hf : g_X;
    out[i] = src[(size_t)(chunk * N_UTT + r) * ND + cc];
}

// ---------------- launch ----------------
extern "C" void kernel_launch(void* const* d_in, const int* in_sizes, int n_in,
                              void* d_out, int out_size) {
    const float* a    = (const float*)d_in[0];
    const float* v    = (const float*)d_in[1];
    const float* l    = (const float*)d_in[2];
    const float* qm   = (const float*)d_in[3];
    const float* adj  = (const float*)d_in[4];
    const float* Wa   = (const float*)d_in[5];
    const float* ba   = (const float*)d_in[6];
    const float* Wv   = (const float*)d_in[7];
    const float* bv   = (const float*)d_in[8];
    const float* Wl   = (const float*)d_in[9];
    const float* bl   = (const float*)d_in[10];
    const float* spk  = (const float*)d_in[11];
    const float* W0   = (const float*)d_in[12];
    const float* b0   = (const float*)d_in[13];
    const float* convW= (const float*)d_in[14];
    float* out = (float*)d_out;

    static bool attr_set = false;
    if (!attr_set) {
        cudaFuncSetAttribute(k_adj_bf16, cudaFuncAttributeMaxDynamicSharedMemorySize,
                             AB_SMEM_BYTES);
        attr_set = true;
    }

    // 1. adj -> bf16 padded; zero bf16 h buffer (pads)
    {
        size_t total = (size_t)KPAD * (KPAD / 8);
        k_conv_adj<<<(unsigned)((total + 255) / 256), 256>>>(adj);
    }
    {
        size_t chunks = (size_t)KPAD * NDP * sizeof(__nv_bfloat16) / 16;
        k_zero_hbf<<<(unsigned)((chunks + 255) / 256), 256>>>();
    }

    // 2. modality projections -> X
    k_gemm_tf32<<<(N_UTT + G2_BM - 1) / G2_BM, 256>>>(a, 0, 300,  N_UTT, 300,  Wa, ba, 0, 0.f, 0,    nullptr, nullptr);
    k_gemm_tf32<<<(N_UTT + G2_BM - 1) / G2_BM, 256>>>(v, 0, 342,  N_UTT, 342,  Wv, bv, 0, 0.f, 2000, nullptr, nullptr);
    k_gemm_tf32<<<(N_UTT + G2_BM - 1) / G2_BM, 256>>>(l, 0, 1024, N_UTT, 1024, Wl, bl, 1, 0.f, 4000, qm, spk);

    // 3. h0 = relu(X @ W0 + b0) -> H0, SUP[:,200:400], Hbf
    k_gemm_tf32<<<(NODES + G2_BM - 1) / G2_BM, 256>>>(nullptr, 1, ND, NODES, ND, W0, b0, 2, 0.f, 0, nullptr, nullptr);

    // 4. GCNII layers
    for (int k = 0; k < NLAYERS; ++k) {
        float theta = logf(0.5f / (float)(k + 1) + 1.0f);
        k_adj_bf16<<<KPAD / AB_BM, 256, AB_SMEM_BYTES>>>();
        k_gemm_tf32<<<(NODES + G2_BM - 1) / G2_BM, 256>>>(
            nullptr, 2, ND2, NODES, ND2, convW + (size_t)k * ND2 * ND,
            nullptr, 3, theta, 0, nullptr, nullptr);
    }

    // 5. gather output
    k_out<<<(N_UTT * 1200 + 255) / 256, 256>>>(out);
}

// round 6
// speedup vs baseline: 3.4003x; 1.7234x over previous
#include <cuda_runtime.h>
#include <cuda_bf16.h>
#include <cstdint>
#include <math.h>

// ---------------- problem constants ----------------
#define N_UTT   2000
#define NODES   6000
#define KPAD    6016     // 47*128
#define ND      200
#define NDP     208
#define ND2     400
#define NLAYERS 8

// ---------------- device scratch ----------------
static __device__ __nv_bfloat16 g_adjBF[(size_t)KPAD * KPAD];    // 72.4 MB
static __device__ __nv_bfloat16 g_Hbf[(size_t)KPAD * NDP];       // h bf16, pads 0
static __device__ float g_X [(size_t)NODES * ND];
static __device__ float g_H0[(size_t)NODES * ND];
static __device__ float g_Hf[(size_t)NODES * ND];
static __device__ float g_SUP[(size_t)NODES * ND2];              // [hi | h0]
static __device__ float g_P[3][(size_t)KPAD * NDP];              // split-K partials (15 MB)
static __device__ __align__(16) float g_zeroF[4];                // zero-initialized

// ---------------- PTX helpers ----------------
__device__ __forceinline__ void cp16(void* s, const void* g) {
    uint32_t sa = (uint32_t)__cvta_generic_to_shared(s);
    asm volatile("cp.async.cg.shared.global [%0], [%1], 16;\n" :: "r"(sa), "l"(g));
}
__device__ __forceinline__ void cp8(void* s, const void* g) {
    uint32_t sa = (uint32_t)__cvta_generic_to_shared(s);
    asm volatile("cp.async.ca.shared.global [%0], [%1], 8;\n" :: "r"(sa), "l"(g));
}
__device__ __forceinline__ void cp_commit() { asm volatile("cp.async.commit_group;\n" ::); }
__device__ __forceinline__ void cp_wait1()  { asm volatile("cp.async.wait_group 1;\n" ::: "memory"); }

__device__ __forceinline__ void ldsm_x4(uint32_t* r, const void* p) {
    uint32_t sa = (uint32_t)__cvta_generic_to_shared(p);
    asm volatile("ldmatrix.sync.aligned.m8n8.x4.shared.b16 {%0,%1,%2,%3}, [%4];\n"
                 : "=r"(r[0]), "=r"(r[1]), "=r"(r[2]), "=r"(r[3]) : "r"(sa));
}
__device__ __forceinline__ void ldsm_x4_t(uint32_t* r, const void* p) {
    uint32_t sa = (uint32_t)__cvta_generic_to_shared(p);
    asm volatile("ldmatrix.sync.aligned.m8n8.x4.trans.shared.b16 {%0,%1,%2,%3}, [%4];\n"
                 : "=r"(r[0]), "=r"(r[1]), "=r"(r[2]), "=r"(r[3]) : "r"(sa));
}
__device__ __forceinline__ void ldsm_x2_t(uint32_t* r, const void* p) {
    uint32_t sa = (uint32_t)__cvta_generic_to_shared(p);
    asm volatile("ldmatrix.sync.aligned.m8n8.x2.trans.shared.b16 {%0,%1}, [%2];\n"
                 : "=r"(r[0]), "=r"(r[1]) : "r"(sa));
}
__device__ __forceinline__ void mma_bf16(float* c, const uint32_t* a, const uint32_t* b) {
    asm volatile("mma.sync.aligned.m16n8k16.row.col.f32.bf16.bf16.f32 "
                 "{%0,%1,%2,%3},{%4,%5,%6,%7},{%8,%9},{%0,%1,%2,%3};\n"
                 : "+f"(c[0]), "+f"(c[1]), "+f"(c[2]), "+f"(c[3])
                 : "r"(a[0]), "r"(a[1]), "r"(a[2]), "r"(a[3]), "r"(b[0]), "r"(b[1]));
}
__device__ __forceinline__ void mma_tf32(float* c, uint32_t a0, uint32_t a1, uint32_t a2,
                                         uint32_t a3, uint32_t b0, uint32_t b1) {
    asm volatile("mma.sync.aligned.m16n8k8.row.col.f32.tf32.tf32.f32 "
                 "{%0,%1,%2,%3},{%4,%5,%6,%7},{%8,%9},{%0,%1,%2,%3};\n"
                 : "+f"(c[0]), "+f"(c[1]), "+f"(c[2]), "+f"(c[3])
                 : "r"(a0), "r"(a1), "r"(a2), "r"(a3), "r"(b0), "r"(b1));
}
__device__ __forceinline__ uint32_t f2tf32(float x) {
    uint32_t r; asm("cvt.rna.tf32.f32 %0, %1;" : "=r"(r) : "f"(x)); return r;
}

// ---------------- adj fp32 -> bf16 padded [KPAD x KPAD] ----------------
__global__ void k_conv_adj(const float* __restrict__ adj) {
    size_t idx = (size_t)blockIdx.x * blockDim.x + threadIdx.x;
    if (idx >= (size_t)KPAD * (KPAD / 8)) return;
    int r  = (int)(idx / (KPAD / 8));
    int c0 = (int)(idx % (KPAD / 8)) * 8;
    __align__(16) __nv_bfloat162 o[4];
    if (r < NODES && c0 + 8 <= NODES) {
        const float4 v0 = *reinterpret_cast<const float4*>(adj + (size_t)r * NODES + c0);
        const float4 v1 = *reinterpret_cast<const float4*>(adj + (size_t)r * NODES + c0 + 4);
        o[0] = __floats2bfloat162_rn(v0.x, v0.y);
        o[1] = __floats2bfloat162_rn(v0.z, v0.w);
        o[2] = __floats2bfloat162_rn(v1.x, v1.y);
        o[3] = __floats2bfloat162_rn(v1.z, v1.w);
    } else {
        #pragma unroll
        for (int j = 0; j < 4; j++) {
            int c = c0 + j * 2;
            float x0 = (r < NODES && c     < NODES) ? adj[(size_t)r * NODES + c]     : 0.f;
            float x1 = (r < NODES && c + 1 < NODES) ? adj[(size_t)r * NODES + c + 1] : 0.f;
            o[j] = __floats2bfloat162_rn(x0, x1);
        }
    }
    *reinterpret_cast<uint4*>(g_adjBF + (size_t)r * KPAD + c0) =
        *reinterpret_cast<const uint4*>(o);
}

__global__ void k_zero_hbf() {
    size_t i = (size_t)blockIdx.x * blockDim.x + threadIdx.x;
    if (i < (size_t)KPAD * NDP * sizeof(__nv_bfloat16) / 16)
        reinterpret_cast<uint4*>(g_Hbf)[i] = make_uint4(0, 0, 0, 0);
}

// ---------------- adj GEMM: split-K partials P[s] = adjBF[:,ks] @ Hbf[ks,:] ------------
// BM=128, BN=208, BK=64, 3 stages, grid (47,3). 256 threads.
// warp tile: wm=warp>>1 (32 rows, 2x m16), wn=warp&1 (104 cols, 13x n8).
#define AJ_BM 128
#define AJ_BK 64
#define AJ_A_EL (AJ_BM * 72)      // [128][64+8]
#define AJ_B_EL (AJ_BK * 216)     // [64][208+8]
#define AJ_STG_EL (AJ_A_EL + AJ_B_EL)
#define AJ_SMEM_BYTES (3 * AJ_STG_EL * 2)    // 138240

__global__ __launch_bounds__(256, 1) void k_adj_bf16() {
    extern __shared__ __nv_bfloat16 aj_sm[];

    const int tid  = threadIdx.x;
    const int lane = tid & 31;
    const int warp = tid >> 5;
    const int wm   = warp >> 1;
    const int wn   = warp & 1;
    const int bm0  = blockIdx.x * AJ_BM;
    const int ksp  = blockIdx.y;
    const int kbase = ksp * 2048;
    const int ITERS = (ksp == 2) ? 30 : 32;   // 2048,2048,1920

    float acc[2][13][4];
    #pragma unroll
    for (int a = 0; a < 2; a++)
        #pragma unroll
        for (int i = 0; i < 13; i++)
            #pragma unroll
            for (int j = 0; j < 4; j++) acc[a][i][j] = 0.f;

    auto fill = [&](int st, int it) {
        const int k0 = kbase + it * AJ_BK;
        __nv_bfloat16* sA = aj_sm + st * AJ_STG_EL;
        __nv_bfloat16* sB = sA + AJ_A_EL;
        #pragma unroll
        for (int v = tid; v < 1024; v += 256) {        // A: 128 x 64
            int r = v >> 3, c = (v & 7) * 8;
            cp16(sA + r * 72 + c, g_adjBF + (size_t)(bm0 + r) * KPAD + k0 + c);
        }
        #pragma unroll
        for (int v = tid; v < 1664; v += 256) {        // B: 64 x 208
            int r = v / 26, nc = (v % 26) * 8;
            cp16(sB + r * 216 + nc, g_Hbf + (size_t)(k0 + r) * NDP + nc);
        }
        cp_commit();
    };

    fill(0, 0);
    if (ITERS > 1) fill(1, 1); else cp_commit();

    #pragma unroll 1
    for (int it = 0; it < ITERS; ++it) {
        cp_wait1();
        __syncthreads();
        const int st = it % 3;
        const __nv_bfloat16* sA = aj_sm + st * AJ_STG_EL;
        const __nv_bfloat16* sB = sA + AJ_A_EL;
        #pragma unroll
        for (int ks = 0; ks < 4; ks++) {
            uint32_t af[2][4];
            #pragma unroll
            for (int mf = 0; mf < 2; mf++)
                ldsm_x4(af[mf], sA + (wm * 32 + mf * 16 + (lane & 15)) * 72
                                   + ks * 16 + ((lane >> 4) << 3));
            uint32_t bf[13][2];
            #pragma unroll
            for (int ng = 0; ng < 6; ng++) {
                uint32_t r[4];
                ldsm_x4_t(r, sB + (ks * 16 + (lane & 15)) * 216
                                + wn * 104 + ng * 16 + ((lane >> 4) << 3));
                bf[ng * 2][0] = r[0];     bf[ng * 2][1] = r[1];
                bf[ng * 2 + 1][0] = r[2]; bf[ng * 2 + 1][1] = r[3];
            }
            {
                uint32_t r[2];
                ldsm_x2_t(r, sB + (ks * 16 + (lane & 15)) * 216 + wn * 104 + 96);
                bf[12][0] = r[0]; bf[12][1] = r[1];
            }
            #pragma unroll
            for (int mf = 0; mf < 2; mf++)
                #pragma unroll
                for (int nf = 0; nf < 13; nf++)
                    mma_bf16(acc[mf][nf], af[mf], bf[nf]);
        }
        // prefetch it+2 into the stage consumed at it-1 (safe after the sync above)
        if (it + 2 < ITERS) fill((it + 2) % 3, it + 2);
        else                cp_commit();
    }

    // partial epilogue -> g_P[ksp]
    float* P = g_P[ksp];
    #pragma unroll
    for (int mf = 0; mf < 2; mf++) {
        const int r0 = bm0 + wm * 32 + mf * 16 + (lane >> 2);
        #pragma unroll
        for (int nf = 0; nf < 13; nf++) {
            int c = wn * 104 + nf * 8 + ((lane & 3) << 1);
            *reinterpret_cast<float2*>(&P[(size_t)r0 * NDP + c]) =
                make_float2(acc[mf][nf][0], acc[mf][nf][1]);
            *reinterpret_cast<float2*>(&P[(size_t)(r0 + 8) * NDP + c]) =
                make_float2(acc[mf][nf][2], acc[mf][nf][3]);
        }
    }
}

// ---------------- reduce partials -> SUP[:,0:200] ----------------
__global__ void k_reduce() {
    int i = blockIdx.x * blockDim.x + threadIdx.x;
    if (i >= NODES * 50) return;
    int r = i / 50, c = (i % 50) * 4;
    size_t o = (size_t)r * NDP + c;
    float4 p0 = *reinterpret_cast<const float4*>(&g_P[0][o]);
    float4 p1 = *reinterpret_cast<const float4*>(&g_P[1][o]);
    float4 p2 = *reinterpret_cast<const float4*>(&g_P[2][o]);
    float4 s = make_float4(p0.x + p1.x + p2.x, p0.y + p1.y + p2.y,
                           p0.z + p1.z + p2.z, p0.w + p1.w + p2.w);
    *reinterpret_cast<float4*>(&g_SUP[(size_t)r * ND2 + c]) = s;
}

// ---------------- tf32 GEMM body: C = A[M,K] @ W[K,200], fused epilogues ----------------
// BM=64, BN=208, BK=32, 3 stages, dynamic smem. 256 threads.
// mode 0: X[row_off+m] = acc + bias
// mode 1: X[row_off+m] = acc + bias + spk_emb[argmax(qmask)]
// mode 2: h0 = relu(acc+bias) -> H0, SUP[:,200:400], Hbf
// mode 3: h  = relu(theta*acc + (1-theta)*(0.9*hi + 0.1*h0)) -> Hf, Hbf
#define G2_BM 64
#define G2_BK 32
#define G2_A_EL (G2_BM * 34)
#define G2_B_EL (G2_BK * 216)
#define G2_STG_EL (G2_A_EL + G2_B_EL)
#define G2_SMEM_BYTES (3 * G2_STG_EL * 4)    // 109056

__device__ __forceinline__ void g2_body(
    float* dyn, const float* __restrict__ A, int lda, int M, int K,
    const float* __restrict__ W, const float* __restrict__ bias,
    int mode, float theta, int row_off,
    const float* __restrict__ qmask, const float* __restrict__ spk_emb)
{
    const int tid  = threadIdx.x;
    const int lane = tid & 31;
    const int warp = tid >> 5;
    const int wm   = warp >> 1;
    const int wn   = warp & 1;
    const int bm0  = blockIdx.x * G2_BM;

    float acc[13][4];
    #pragma unroll
    for (int i = 0; i < 13; i++)
        #pragma unroll
        for (int j = 0; j < 4; j++) acc[i][j] = 0.f;

    auto fill = [&](int st, int it) {
        const int k0 = it * G2_BK;
        float* shA = dyn + st * G2_STG_EL;
        float* shB = shA + G2_A_EL;
        #pragma unroll
        for (int v = tid; v < 1024; v += 256) {      // A: 64 x 32 in 8B chunks
            int m = v >> 4, kp = (v & 15) * 2;
            int gm = bm0 + m, gk = k0 + kp;
            const float* src = (gm < M && gk < K) ? &A[(size_t)gm * lda + gk] : g_zeroF;
            cp8(shA + m * 34 + kp, src);
        }
        for (int v = tid; v < 3328; v += 256) {      // B: 32 x 208 in 8B chunks
            int k = v / 104, np = (v % 104) * 2;
            int gk = k0 + k;
            const float* src = (gk < K && np < ND) ? &W[(size_t)gk * ND + np] : g_zeroF;
            cp8(shB + k * 216 + np, src);
        }
        cp_commit();
    };

    const int ITERS = (K + G2_BK - 1) / G2_BK;
    fill(0, 0);
    if (ITERS > 1) fill(1, 1); else cp_commit();

    const int mrow = wm * 16 + (lane >> 2);
    #pragma unroll 1
    for (int it = 0; it < ITERS; ++it) {
        cp_wait1();
        __syncthreads();
        const int st = it % 3;
        const float* shA = dyn + st * G2_STG_EL;
        const float* shB = shA + G2_A_EL;
        #pragma unroll
        for (int kb = 0; kb < G2_BK; kb += 8) {
            const int kk = kb + (lane & 3);
            uint32_t a0 = f2tf32(shA[mrow * 34 + kk]);
            uint32_t a1 = f2tf32(shA[(mrow + 8) * 34 + kk]);
            uint32_t a2 = f2tf32(shA[mrow * 34 + kk + 4]);
            uint32_t a3 = f2tf32(shA[(mrow + 8) * 34 + kk + 4]);
            #pragma unroll
            for (int nf = 0; nf < 13; nf++) {
                int nc = wn * 104 + nf * 8 + (lane >> 2);
                uint32_t b0 = f2tf32(shB[(kb + (lane & 3)) * 216 + nc]);
                uint32_t b1 = f2tf32(shB[(kb + 4 + (lane & 3)) * 216 + nc]);
                mma_tf32(acc[nf], a0, a1, a2, a3, b0, b1);
            }
        }
        if (it + 2 < ITERS) fill((it + 2) % 3, it + 2);
        else                cp_commit();
    }

    // fused epilogue (c always even, pair stays < ND when c < ND)
    const int mloc = wm * 16 + (lane >> 2);
    #pragma unroll
    for (int nf = 0; nf < 13; nf++) {
        int c = wn * 104 + nf * 8 + ((lane & 3) << 1);
        if (c >= ND) continue;
        #pragma unroll
        for (int half = 0; half < 2; half++) {
            int m = bm0 + mloc + half * 8;
            if (m >= M) continue;
            float v0 = acc[nf][half * 2], v1 = acc[nf][half * 2 + 1];
            if (mode <= 1) {
                float x0 = v0 + bias[c], x1 = v1 + bias[c + 1];
                if (mode == 1) {
                    int b = m / 100, t = m % 100;
                    float q0 = qmask[(t * 20 + b) * 2];
                    float q1 = qmask[(t * 20 + b) * 2 + 1];
                    int idx = (q1 > q0) ? 1 : 0;
                    x0 += spk_emb[idx * ND + c];
                    x1 += spk_emb[idx * ND + c + 1];
                }
                *reinterpret_cast<float2*>(&g_X[(size_t)(row_off + m) * ND + c]) =
                    make_float2(x0, x1);
            } else if (mode == 2) {
                float x0 = fmaxf(v0 + bias[c], 0.f);
                float x1 = fmaxf(v1 + bias[c + 1], 0.f);
                *reinterpret_cast<float2*>(&g_H0[(size_t)m * ND + c]) = make_float2(x0, x1);
                *reinterpret_cast<float2*>(&g_SUP[(size_t)m * ND2 + ND + c]) = make_float2(x0, x1);
                *reinterpret_cast<__nv_bfloat162*>(&g_Hbf[(size_t)m * NDP + c]) =
                    __floats2bfloat162_rn(x0, x1);
            } else {
                float2 hi  = *reinterpret_cast<const float2*>(&g_SUP[(size_t)m * ND2 + c]);
                float2 h0v = *reinterpret_cast<const float2*>(&g_H0[(size_t)m * ND + c]);
                float x0 = fmaxf(theta * v0 + (1.f - theta) * (0.9f * hi.x + 0.1f * h0v.x), 0.f);
                float x1 = fmaxf(theta * v1 + (1.f - theta) * (0.9f * hi.y + 0.1f * h0v.y), 0.f);
                *reinterpret_cast<float2*>(&g_Hf[(size_t)m * ND + c]) = make_float2(x0, x1);
                *reinterpret_cast<__nv_bfloat162*>(&g_Hbf[(size_t)m * NDP + c]) =
                    __floats2bfloat162_rn(x0, x1);
            }
        }
    }
}

// merged modality projections: grid (32, 3)
__global__ __launch_bounds__(256, 1) void k_proj(
    const float* __restrict__ a, const float* __restrict__ v, const float* __restrict__ l,
    const float* __restrict__ Wa, const float* __restrict__ ba,
    const float* __restrict__ Wv, const float* __restrict__ bv,
    const float* __restrict__ Wl, const float* __restrict__ bl,
    const float* __restrict__ qm, const float* __restrict__ spk)
{
    extern __shared__ float dyn[];
    if (blockIdx.y == 0)
        g2_body(dyn, a, 300,  N_UTT, 300,  Wa, ba, 0, 0.f, 0,    nullptr, nullptr);
    else if (blockIdx.y == 1)
        g2_body(dyn, v, 342,  N_UTT, 342,  Wv, bv, 0, 0.f, 2000, nullptr, nullptr);
    else
        g2_body(dyn, l, 1024, N_UTT, 1024, Wl, bl, 1, 0.f, 4000, qm, spk);
}

// generic tf32 GEMM (h0 + layer updates). asel: 1 -> g_X, 2 -> g_SUP
__global__ __launch_bounds__(256, 1) void k_gemm_tf32(
    int asel, int lda, int M, int K,
    const float* __restrict__ W, const float* __restrict__ bias,
    int mode, float theta)
{
    extern __shared__ float dyn[];
    const float* A = (asel == 1) ? g_X : g_SUP;
    g2_body(dyn, A, lda, M, K, W, bias, mode, theta, 0, nullptr, nullptr);
}

// ---------------- output assembly: [2000, 1200] ----------------
__global__ void k_out(float* __restrict__ out) {
    int i = blockIdx.x * blockDim.x + threadIdx.x;
    if (i >= N_UTT * 1200) return;
    int r = i / 1200, c = i % 1200;
    int seg = c / ND, cc = c % ND;
    int chunk = seg >> 1;
    const float* src = (seg & 1) ? g_Hf : g_X;
    out[i] = src[(size_t)(chunk * N_UTT + r) * ND + cc];
}

// ---------------- launch ----------------
extern "C" void kernel_launch(void* const* d_in, const int* in_sizes, int n_in,
                              void* d_out, int out_size) {
    const float* a    = (const float*)d_in[0];
    const float* v    = (const float*)d_in[1];
    const float* l    = (const float*)d_in[2];
    const float* qm   = (const float*)d_in[3];
    const float* adj  = (const float*)d_in[4];
    const float* Wa   = (const float*)d_in[5];
    const float* ba   = (const float*)d_in[6];
    const float* Wv   = (const float*)d_in[7];
    const float* bv   = (const float*)d_in[8];
    const float* Wl   = (const float*)d_in[9];
    const float* bl   = (const float*)d_in[10];
    const float* spk  = (const float*)d_in[11];
    const float* W0   = (const float*)d_in[12];
    const float* b0   = (const float*)d_in[13];
    const float* convW= (const float*)d_in[14];
    float* out = (float*)d_out;

    cudaFuncSetAttribute(k_adj_bf16, cudaFuncAttributeMaxDynamicSharedMemorySize, AJ_SMEM_BYTES);
    cudaFuncSetAttribute(k_proj, cudaFuncAttributeMaxDynamicSharedMemorySize, G2_SMEM_BYTES);
    cudaFuncSetAttribute(k_gemm_tf32, cudaFuncAttributeMaxDynamicSharedMemorySize, G2_SMEM_BYTES);

    // 1. adj -> bf16 padded; zero bf16 h buffer
    {
        size_t total = (size_t)KPAD * (KPAD / 8);
        k_conv_adj<<<(unsigned)((total + 255) / 256), 256>>>(adj);
    }
    {
        size_t chunks = (size_t)KPAD * NDP * sizeof(__nv_bfloat16) / 16;
        k_zero_hbf<<<(unsigned)((chunks + 255) / 256), 256>>>();
    }

    // 2. all three modality projections in one launch
    {
        dim3 g((N_UTT + G2_BM - 1) / G2_BM, 3);
        k_proj<<<g, 256, G2_SMEM_BYTES>>>(a, v, l, Wa, ba, Wv, bv, Wl, bl, qm, spk);
    }

    // 3. h0 = relu(X @ W0 + b0) -> H0, SUP[:,200:400], Hbf
    k_gemm_tf32<<<(NODES + G2_BM - 1) / G2_BM, 256, G2_SMEM_BYTES>>>(
        1, ND, NODES, ND, W0, b0, 2, 0.f);

    // 4. GCNII layers
    for (int k = 0; k < NLAYERS; ++k) {
        float theta = logf(0.5f / (float)(k + 1) + 1.0f);
        dim3 ga(KPAD / AJ_BM, 3);
        k_adj_bf16<<<ga, 256, AJ_SMEM_BYTES>>>();
        k_reduce<<<(NODES * 50 + 255) / 256, 256>>>();
        k_gemm_tf32<<<(NODES + G2_BM - 1) / G2_BM, 256, G2_SMEM_BYTES>>>(
            2, ND2, NODES, ND2, convW + (size_t)k * ND2 * ND, nullptr, 3, theta);
    }

    // 5. gather output
    k_out<<<(N_UTT * 1200 + 255) / 256, 256>>>(out);
}